// round 16
// baseline (speedup 1.0000x reference)
#include <cuda_runtime.h>
#include <cuda_fp16.h>
#include <cstdint>

#define BB   8
#define NN   8192
#define EE   262144
#define FIN  64
#define HH   128
#define FOUT 32
#define TOT  (BB*NN)   // 65536 rows total
#define CAP  128       // bucket capacity; deg ~ Poisson(32), max over 65K rows ~ 70

typedef unsigned long long ull;
typedef unsigned int uint;

// ---------------- device scratch (no allocations allowed) ----------------
__device__ uint  g_h0p[(size_t)TOT*(HH/2)];   // h0 as fp16x2 pairs
__device__ uint  g_hcp[(size_t)TOT*(HH/2)];   // hc as fp16x2 pairs
__device__ uint  g_h1p[(size_t)TOT*(HH/2)];   // h1 as fp16x2 pairs
__device__ float g_h2[(size_t)TOT*HH];
__device__ int   g_cnt[TOT];
__device__ uint  g_bkt[(size_t)TOT*CAP];      // bucketed edges: [fp16 val | 16-bit col]
__device__ float g_stat[6*HH];                // [stage][sum|sumsq][H], stages 0..2
__device__ float g_ba[HH];
__device__ float g_bb[HH];
__device__ float g_bo[FOUT];
// fragment-order split-fp16 weight tables: uint4 {bh0,bh1,bl0,bl1} per (ntile,kstep,lane)
__device__ uint4 g_bf0[(HH/8)*(FIN/16)*32];   // W0:  K=64,  N=128
__device__ uint4 g_bfa[(HH/8)*(HH/16)*32];    // Wa:  K=128, N=128
__device__ uint4 g_bfb[(HH/8)*(HH/16)*32];    // Wb:  K=128, N=128
__device__ uint4 g_bfo[(FOUT/8)*(HH/16)*32];  // Wo:  K=128, N=32

// ---------------- side stream for fork-join overlap (created pre-main) -----------
struct SideCtx {
    cudaStream_t s = 0;
    cudaEvent_t  eFork = 0, eJoin = 0;
    bool ok = false;
    SideCtx() {
        ok = (cudaStreamCreateWithFlags(&s, cudaStreamNonBlocking) == cudaSuccess) &&
             (cudaEventCreateWithFlags(&eFork, cudaEventDisableTiming) == cudaSuccess) &&
             (cudaEventCreateWithFlags(&eJoin, cudaEventDisableTiming) == cudaSuccess);
    }
};
static SideCtx g_side;

__device__ __forceinline__ float2 h2f(uint p) {
    return __half22float2(*reinterpret_cast<__half2*>(&p));
}
__device__ __forceinline__ void mma16816(float* d, const uint* a, uint b0, uint b1) {
    asm volatile("mma.sync.aligned.m16n8k16.row.col.f32.f16.f16.f32 "
        "{%0,%1,%2,%3}, {%4,%5,%6,%7}, {%8,%9}, {%0,%1,%2,%3};\n"
        : "+f"(d[0]), "+f"(d[1]), "+f"(d[2]), "+f"(d[3])
        : "r"(a[0]), "r"(a[1]), "r"(a[2]), "r"(a[3]), "r"(b0), "r"(b1));
}
__device__ __forceinline__ void ldsm_x4(uint* r, uint addr) {
    asm volatile("ldmatrix.sync.aligned.m8n8.x4.shared.b16 {%0,%1,%2,%3}, [%4];"
        : "=r"(r[0]), "=r"(r[1]), "=r"(r[2]), "=r"(r[3]) : "r"(addr));
}
__device__ __forceinline__ uint smem_u32(const void* p) {
    uint a;
    asm("{ .reg .u64 t; cvta.to.shared.u64 t, %1; cvt.u32.u64 %0, t; }" : "=r"(a) : "l"(p));
    return a;
}
// split fp32 weight quad -> packed split-fp16 fragment
__device__ __forceinline__ uint4 pack_split(float w00, float w01, float w10, float w11) {
    __half h00 = __float2half_rn(w00), h01 = __float2half_rn(w01);
    __half h10 = __float2half_rn(w10), h11 = __float2half_rn(w11);
    __half l00 = __float2half_rn(w00 - __half2float(h00));
    __half l01 = __float2half_rn(w01 - __half2float(h01));
    __half l10 = __float2half_rn(w10 - __half2float(h10));
    __half l11 = __float2half_rn(w11 - __half2float(h11));
    __half2 bh0 = __halves2half2(h00, h01), bh1 = __halves2half2(h10, h11);
    __half2 bl0 = __halves2half2(l00, l01), bl1 = __halves2half2(l10, l11);
    uint4 v;
    v.x = *(uint*)&bh0; v.y = *(uint*)&bh1; v.z = *(uint*)&bl0; v.w = *(uint*)&bl1;
    return v;
}
// BN affine coefficients from accumulated stats
__device__ __forceinline__ void bn_st(int stage, int f, const float* bnw, const float* bnb,
                                      float& s, float& t) {
    float cnt = (float)TOT;
    float sum = g_stat[stage*2*HH + f];
    float sq  = g_stat[stage*2*HH + HH + f];
    float m = sum / cnt;
    float v = sq / cnt - m*m;
    float inv = rsqrtf(v + 1e-5f);
    s = bnw[f] * inv;
    t = bnb[f] - m * s;
}

// ---------------- zero bucket counters (side branch, feeds scatter) ----------------
__global__ void zero_cnt_kernel()
{
    int gid = blockIdx.x * 256 + threadIdx.x;
    if (gid < TOT) g_cnt[gid] = 0;
}

// ---------------- prep0: W0 fragment table + accumulator zero + bias seeds ---------
// grid = 17 blocks x 128: blocks 0..15 build bfrag for nt=bid (4 warps = 4 ks),
// block 16 zeros g_stat/g_ba and seeds g_bb/g_bo.
__global__ void prep0_kernel(const float* __restrict__ W0, uint4* __restrict__ out,
                             const float* __restrict__ b1, const float* __restrict__ b2)
{
    int bid = blockIdx.x, tid = threadIdx.x;
    if (bid < HH/8) {
        constexpr int KS = FIN/16;     // 4
        int nt = bid;
        int ks = tid >> 5, lane = tid & 31;
        int g = lane >> 2, t = lane & 3;
        int n = nt*8 + g, k0 = ks*16 + 2*t;
        uint4 v = pack_split(W0[(k0+0)*HH + n], W0[(k0+1)*HH + n],
                             W0[(k0+8)*HH + n], W0[(k0+9)*HH + n]);
        out[(nt*KS + ks)*32 + lane] = v;
    } else {
        #pragma unroll
        for (int i = tid; i < 6*HH; i += 128) g_stat[i] = 0.f;
        g_ba[tid] = 0.f;                   // fold0_bfrag adds seed + t0@(W02@Wc)
        g_bb[tid] = b1[tid];               // fold_bfrag(1) adds t1 @ W1
        if (tid < FOUT) g_bo[tid] = b2[tid];
    }
}

// ---------------- fused BN0-fold + W02@Wc + fragment emit ----------------
// grid = HH/16 = 8 blocks x 256. Block ksg computes Wa rows [16ksg,16ksg+16) in smem
// and emits the ks=ksg slice of the fragment table; also accumulates g_ba.
__global__ __launch_bounds__(256)
void fold0_bfrag_kernel(const float* __restrict__ bnw, const float* __restrict__ bnb,
                        const float* __restrict__ W02, const float* __restrict__ Wc,
                        const float* __restrict__ b02, const float* __restrict__ bc,
                        uint4* __restrict__ out)
{
    extern __shared__ float sh[];
    float* Wcs  = sh;                 // [HH*HH]
    float* W02s = sh + HH*HH;         // [16*HH]
    float* ms   = W02s + 16*HH;       // [16*HH] raw (W02@Wc) rows
    float* ss   = ms + 16*HH;         // [16]
    float* ts   = ss + 16;            // [16]
    int ksg = blockIdx.x, tid = threadIdx.x;

    #pragma unroll 4
    for (int i = tid; i < HH*HH/4; i += 256) ((float4*)Wcs)[i] = ((const float4*)Wc)[i];
    for (int i = tid; i < 16*HH/4; i += 256)
        ((float4*)W02s)[i] = ((const float4*)(W02 + ksg*16*HH))[i];
    if (tid < 16) { float s, t; bn_st(0, ksg*16 + tid, bnw, bnb, s, t); ss[tid] = s; ts[tid] = t; }
    __syncthreads();

    for (int idx = tid; idx < 16*HH; idx += 256) {
        int i = idx >> 7, k = idx & 127;
        float acc = 0.f;
        #pragma unroll 8
        for (int j = 0; j < HH; j++) acc = fmaf(W02s[i*HH + j], Wcs[j*HH + k], acc);
        ms[idx] = acc;
    }
    __syncthreads();

    if (tid < HH) {
        float acc = 0.f;
        #pragma unroll
        for (int i = 0; i < 16; i++) acc = fmaf(ts[i], ms[i*HH + tid], acc);
        if (ksg == 0) {   // seed: bc + b02 @ Wc (once)
            float s = bc[tid];
            #pragma unroll 8
            for (int f = 0; f < HH; f++) s = fmaf(b02[f], Wcs[f*HH + tid], s);
            acc += s;
        }
        atomicAdd(&g_ba[tid], acc);
    }

    constexpr int KS = HH/16;   // 8
    for (int ent = tid; ent < 16*32; ent += 256) {
        int nt = ent >> 5, lane = ent & 31;
        int g = lane >> 2, t4 = lane & 3;
        int n = nt*8 + g;
        int r0 = 2*t4, r1 = 2*t4 + 1, r2 = 2*t4 + 8, r3 = 2*t4 + 9;
        uint4 v = pack_split(ss[r0]*ms[r0*HH + n], ss[r1]*ms[r1*HH + n],
                             ss[r2]*ms[r2*HH + n], ss[r3]*ms[r3*HH + n]);
        out[(nt*KS + ksg)*32 + lane] = v;
    }
}

// ---------------- fused BN-fold + fragment build + bias (stages 1,2) ----------------
// grid (N/8, KS/4), block 128 (4 warps = 4 ks values)
template<int K, int N>
__global__ void fold_bfrag_kernel(const float* __restrict__ bnw, const float* __restrict__ bnb,
                                  int stage, const float* __restrict__ W,
                                  uint4* __restrict__ out, float* __restrict__ bias)
{
    constexpr int KS = K/16;
    int nt = blockIdx.x;
    int ks = blockIdx.y*4 + (threadIdx.x >> 5);
    int lane = threadIdx.x & 31;
    int g = lane >> 2, t = lane & 3;
    int n = nt*8 + g, k0 = ks*16 + 2*t;
    float s0,t0,s1,t1,s2,t2,s3,t3;
    bn_st(stage, k0+0, bnw, bnb, s0, t0);
    bn_st(stage, k0+1, bnw, bnb, s1, t1);
    bn_st(stage, k0+8, bnw, bnb, s2, t2);
    bn_st(stage, k0+9, bnw, bnb, s3, t3);
    float m00 = W[(k0+0)*N + n], m01 = W[(k0+1)*N + n];
    float m10 = W[(k0+8)*N + n], m11 = W[(k0+9)*N + n];
    uint4 v = pack_split(s0*m00, s1*m01, s2*m10, s3*m11);
    out[(nt*KS + ks)*32 + lane] = v;
    float bcv = t0*m00 + t1*m01 + t2*m10 + t3*m11;
    bcv += __shfl_xor_sync(0xffffffffu, bcv, 1);
    bcv += __shfl_xor_sync(0xffffffffu, bcv, 2);
    if (t == 0) atomicAdd(&bias[n], bcv);
}

// ---------------- single-pass bucketed edge build (4 edges/thread) ----------------
__global__ void scatter_kernel(const int* __restrict__ rows, const int* __restrict__ cols,
                               const float* __restrict__ vals)
{
    int gid = blockIdx.x * 256 + threadIdx.x;        // grid covers (BB*EE)/4
    int e0 = gid * 4;
    if (e0 >= BB*EE) return;
    int base = (e0 >> 18) * NN;                      // 4 edges never cross a batch
    int4   r = *(const int4*)(rows + e0);
    int4   c = *(const int4*)(cols + e0);
    float4 v = *(const float4*)(vals + e0);
    int i0 = base + r.x, i1 = base + r.y, i2 = base + r.z, i3 = base + r.w;
    int p0 = atomicAdd(&g_cnt[i0], 1);
    int p1 = atomicAdd(&g_cnt[i1], 1);
    int p2 = atomicAdd(&g_cnt[i2], 1);
    int p3 = atomicAdd(&g_cnt[i3], 1);
    uint h0 = (uint)__half_as_ushort(__float2half_rn(v.x));
    uint h1 = (uint)__half_as_ushort(__float2half_rn(v.y));
    uint h2 = (uint)__half_as_ushort(__float2half_rn(v.z));
    uint h3 = (uint)__half_as_ushort(__float2half_rn(v.w));
    if (p0 < CAP) g_bkt[(size_t)i0*CAP + p0] = (h0 << 16) | (uint)c.x;
    if (p1 < CAP) g_bkt[(size_t)i1*CAP + p1] = (h1 << 16) | (uint)c.y;
    if (p2 < CAP) g_bkt[(size_t)i2*CAP + p2] = (h2 << 16) | (uint)c.z;
    if (p3 < CAP) g_bkt[(size_t)i3*CAP + p3] = (h3 << 16) | (uint)c.w;
}

// ---------------- SpMM aggregate (fp16 gather) + norm + mask + relu + bnc stats --------
__global__ void agg_kernel(const int* __restrict__ nn)
{
    __shared__ float s_ls[HH], s_lq[HH];
    int tid = threadIdx.x, w = tid >> 5, lane = tid & 31;
    for (int i = tid; i < HH; i += 128) { s_ls[i] = 0.f; s_lq[i] = 0.f; }
    __syncthreads();

    float ls[4] = {0,0,0,0}, lq[4] = {0,0,0,0};
    #pragma unroll 1
    for (int ri = 0; ri < 2; ri++) {
        int idx = blockIdx.x * 8 + ri*4 + w;
        int b = idx >> 13, r = idx & (NN - 1);
        int len = min(g_cnt[idx], CAP);
        const uint2* hcb = (const uint2*)g_hcp + (size_t)b*NN*32;
        const uint*  ep  = g_bkt + (size_t)idx*CAP;

        float a0=0.f, a1=0.f, a2=0.f, a3=0.f, ds=0.f;
        for (int e0 = 0; e0 < len; e0 += 32) {
            uint my = (e0 + lane < len) ? ep[e0 + lane] : 0u;
            int m = min(32, len - e0);
            int t = 0;
            for (; t + 2 <= m; t += 2) {
                uint ea = __shfl_sync(0xffffffffu, my, t);
                uint eb = __shfl_sync(0xffffffffu, my, t+1);
                float va = __half2float(__ushort_as_half((unsigned short)(ea >> 16)));
                float vb = __half2float(__ushort_as_half((unsigned short)(eb >> 16)));
                uint2 ha = hcb[(size_t)(ea & 0xFFFFu)*32 + lane];
                uint2 hb = hcb[(size_t)(eb & 0xFFFFu)*32 + lane];
                float2 fa0 = h2f(ha.x), fa1 = h2f(ha.y);
                float2 fb0 = h2f(hb.x), fb1 = h2f(hb.y);
                a0 = fmaf(va, fa0.x, a0);  a1 = fmaf(va, fa0.y, a1);
                a2 = fmaf(va, fa1.x, a2);  a3 = fmaf(va, fa1.y, a3);
                a0 = fmaf(vb, fb0.x, a0);  a1 = fmaf(vb, fb0.y, a1);
                a2 = fmaf(vb, fb1.x, a2);  a3 = fmaf(vb, fb1.y, a3);
                ds += va + vb;
            }
            if (t < m) {
                uint ea = __shfl_sync(0xffffffffu, my, t);
                float va = __half2float(__ushort_as_half((unsigned short)(ea >> 16)));
                uint2 ha = hcb[(size_t)(ea & 0xFFFFu)*32 + lane];
                float2 fa0 = h2f(ha.x), fa1 = h2f(ha.y);
                a0 = fmaf(va, fa0.x, a0);  a1 = fmaf(va, fa0.y, a1);
                a2 = fmaf(va, fa1.x, a2);  a3 = fmaf(va, fa1.y, a3);
                ds += va;
            }
        }
        float inv = 1.f / fmaxf(ds, 1.f);
        bool dead = (r >= nn[b]);
        float o0 = dead ? 0.f : fmaxf(a0*inv, 0.f);
        float o1 = dead ? 0.f : fmaxf(a1*inv, 0.f);
        float o2 = dead ? 0.f : fmaxf(a2*inv, 0.f);
        float o3 = dead ? 0.f : fmaxf(a3*inv, 0.f);
        __half2 q0 = __floats2half2_rn(o0, o1);
        __half2 q1 = __floats2half2_rn(o2, o3);
        uint2 qq; qq.x = *(uint*)&q0; qq.y = *(uint*)&q1;
        ((uint2*)g_h1p)[(size_t)idx*32 + lane] = qq;
        ls[0]+=o0; lq[0]+=o0*o0;  ls[1]+=o1; lq[1]+=o1*o1;
        ls[2]+=o2; lq[2]+=o2*o2;  ls[3]+=o3; lq[3]+=o3*o3;
    }
    #pragma unroll
    for (int q = 0; q < 4; q++) {
        atomicAdd(&s_ls[lane*4+q], ls[q]);
        atomicAdd(&s_lq[lane*4+q], lq[q]);
    }
    __syncthreads();
    for (int i = tid; i < HH; i += 128) {
        atomicAdd(&g_stat[1*2*HH + i],      s_ls[i]);
        atomicAdd(&g_stat[1*2*HH + HH + i], s_lq[i]);
    }
}

// ---------------- tensor-core GEMM (ldmatrix A loads) ----------------
// IN16=false: A fp32, 3-term split (Ah@Wh + Ah@Wl + Al@Wh), error ~ fp32.
// IN16=true:  A fp16 (stored), 2-term (A@Wh + A@Wl).
template<int BM, int K, int NC, bool RELU, int STAGE, bool OUT16, bool IN16>
__global__ __launch_bounds__(256, (BM == 64) ? 3 : 2)
void gemm_tc(const void* __restrict__ Av, const uint4* __restrict__ BF,
             const float* __restrict__ bias, void* __restrict__ Cv)
{
    constexpr int KS  = K / 16;
    constexpr int WN  = (NC == 32) ? 1 : 2;     // warps along N
    constexpr int WM  = 8 / WN;                 // warps along M
    constexpr int MF  = BM / WM / 16;           // m16 frags per warp
    constexpr int NF  = NC / WN / 8;            // n8 frags per warp
    constexpr int AST = K + 8;                  // half stride: 2*AST % 128B == 16

    extern __shared__ __half sh2[];
    __half* Ah = sh2;                           // [BM][AST]
    __half* Al = sh2 + (IN16 ? 0 : BM*AST);
    __shared__ float s_ls[HH], s_lq[HH];

    int tid = threadIdx.x;
    size_t row0 = (size_t)blockIdx.x * BM;

    if (IN16) {
        const uint4* Ag = (const uint4*)((const __half*)Av + row0*K);
        #pragma unroll 4
        for (int i = tid; i < BM*K/8; i += 256) {
            uint4 v = Ag[i];
            int r = (i*8)/K, c = (i*8)%K;
            *(uint4*)&Ah[r*AST + c] = v;
        }
    } else {
        const float4* Ag = (const float4*)((const float*)Av + row0*K);
        #pragma unroll 4
        for (int i = tid; i < BM*K/4; i += 256) {
            float4 v = Ag[i];
            int r = (i*4)/K, c = (i*4)%K;
            __half h0 = __float2half_rn(v.x), h1 = __float2half_rn(v.y);
            __half h2v = __float2half_rn(v.z), h3 = __float2half_rn(v.w);
            __half* ap = Ah + r*AST + c;
            ap[0] = h0; ap[1] = h1; ap[2] = h2v; ap[3] = h3;
            __half* lp = Al + r*AST + c;
            lp[0] = __float2half_rn(v.x - __half2float(h0));
            lp[1] = __float2half_rn(v.y - __half2float(h1));
            lp[2] = __float2half_rn(v.z - __half2float(h2v));
            lp[3] = __float2half_rn(v.w - __half2float(h3));
        }
    }
    if (STAGE >= 0) for (int i = tid; i < HH; i += 256) { s_ls[i] = 0.f; s_lq[i] = 0.f; }
    __syncthreads();

    int wid = tid >> 5, lane = tid & 31;
    int wm = wid % WM, wn = wid / WM;
    int g = lane >> 2, t = lane & 3;

    // ldmatrix per-lane base address (within this warp's row slice)
    int q = lane >> 3, rr = lane & 7;
    uint lrow = (uint)(rr + (q & 1)*8);
    uint lcol = (uint)((q >> 1)*8);
    uint aBase = smem_u32(Ah) + ((wm*MF*16 + lrow)*AST + lcol) * 2;
    uint alBase = aBase + (IN16 ? 0u : (uint)(BM*AST*2));

    float acc[MF][NF][4];
    #pragma unroll
    for (int mf = 0; mf < MF; mf++)
        #pragma unroll
        for (int nf = 0; nf < NF; nf++)
            #pragma unroll
            for (int qq = 0; qq < 4; qq++) acc[mf][nf][qq] = 0.f;

    #pragma unroll
    for (int ks = 0; ks < KS; ks++) {
        uint ah[MF][4], al[MF][4];
        #pragma unroll
        for (int mf = 0; mf < MF; mf++) {
            uint off = (uint)((mf*16*AST + ks*16) * 2);
            ldsm_x4(ah[mf], aBase + off);
            if (!IN16) ldsm_x4(al[mf], alBase + off);
        }
        #pragma unroll
        for (int nf = 0; nf < NF; nf++) {
            int nt = wn*NF + nf;
            uint4 b = BF[(nt*KS + ks)*32 + lane];
            #pragma unroll
            for (int mf = 0; mf < MF; mf++) {
                mma16816(acc[mf][nf], ah[mf], b.x, b.y);             // A(h) @ Wh
                mma16816(acc[mf][nf], ah[mf], b.z, b.w);             // A(h) @ Wl
                if (!IN16) mma16816(acc[mf][nf], al[mf], b.x, b.y);  // Al @ Wh
            }
        }
    }

    // epilogue: bias, relu, store, stats
    #pragma unroll
    for (int nf = 0; nf < NF; nf++) {
        int c = wn*NF*8 + nf*8 + 2*t;
        float b0v = bias[c], b1v = bias[c+1];
        float ls0 = 0.f, lq0 = 0.f, ls1 = 0.f, lq1 = 0.f;
        #pragma unroll
        for (int mf = 0; mf < MF; mf++) {
            float v00 = acc[mf][nf][0] + b0v, v01 = acc[mf][nf][1] + b1v;
            float v10 = acc[mf][nf][2] + b0v, v11 = acc[mf][nf][3] + b1v;
            if (RELU) {
                v00 = fmaxf(v00, 0.f); v01 = fmaxf(v01, 0.f);
                v10 = fmaxf(v10, 0.f); v11 = fmaxf(v11, 0.f);
            }
            size_t r0 = row0 + wm*MF*16 + mf*16 + g, r1 = r0 + 8;
            if (OUT16) {
                __half2 p0 = __float22half2_rn(make_float2(v00, v01));
                __half2 p1 = __float22half2_rn(make_float2(v10, v11));
                ((uint*)Cv)[r0*(NC/2) + c/2] = *(uint*)&p0;
                ((uint*)Cv)[r1*(NC/2) + c/2] = *(uint*)&p1;
            } else {
                *(float2*)&((float*)Cv)[r0*NC + c] = make_float2(v00, v01);
                *(float2*)&((float*)Cv)[r1*NC + c] = make_float2(v10, v11);
            }
            if (STAGE >= 0) {
                ls0 += v00 + v10; lq0 += v00*v00 + v10*v10;
                ls1 += v01 + v11; lq1 += v01*v01 + v11*v11;
            }
        }
        if (STAGE >= 0) {
            #pragma unroll
            for (int o = 4; o <= 16; o <<= 1) {
                ls0 += __shfl_xor_sync(0xffffffffu, ls0, o);
                lq0 += __shfl_xor_sync(0xffffffffu, lq0, o);
                ls1 += __shfl_xor_sync(0xffffffffu, ls1, o);
                lq1 += __shfl_xor_sync(0xffffffffu, lq1, o);
            }
            if (lane < 4) {
                atomicAdd(&s_ls[c], ls0); atomicAdd(&s_lq[c], lq0);
                atomicAdd(&s_ls[c+1], ls1); atomicAdd(&s_lq[c+1], lq1);
            }
        }
    }

    if (STAGE >= 0) {
        __syncthreads();
        for (int i = tid; i < NC; i += 256) {
            atomicAdd(&g_stat[STAGE*2*HH + i],      s_ls[i]);
            atomicAdd(&g_stat[STAGE*2*HH + HH + i], s_lq[i]);
        }
    }
}

// ---------------- host launcher ----------------
extern "C" void kernel_launch(void* const* d_in, const int* in_sizes, int n_in,
                              void* d_out, int out_size)
{
    const float* x    = (const float*)d_in[0];
    const int*   erow = (const int*)  d_in[1];
    const int*   ecol = (const int*)  d_in[2];
    const float* evl  = (const float*)d_in[3];
    const int*   nn   = (const int*)  d_in[4];
    const float* W0   = (const float*)d_in[5];
    const float* b0   = (const float*)d_in[6];
    const float* W02  = (const float*)d_in[7];
    const float* b02  = (const float*)d_in[8];
    const float* Wc   = (const float*)d_in[9];
    const float* bc   = (const float*)d_in[10];
    const float* W1   = (const float*)d_in[11];
    const float* b1   = (const float*)d_in[12];
    const float* W2   = (const float*)d_in[13];
    const float* b2   = (const float*)d_in[14];
    const float* bn0w = (const float*)d_in[15];
    const float* bn0b = (const float*)d_in[16];
    const float* bncw = (const float*)d_in[17];
    const float* bncb = (const float*)d_in[18];
    const float* bn1w = (const float*)d_in[19];
    const float* bn1b = (const float*)d_in[20];
    float* out = (float*)d_out;

    float *p_h2, *p_ba, *p_bb, *p_bo;
    uint  *p_h0p, *p_hcp, *p_h1p;
    uint4 *p_bf0, *p_bfa, *p_bfb, *p_bfo;
    cudaGetSymbolAddress((void**)&p_h0p, g_h0p);
    cudaGetSymbolAddress((void**)&p_hcp, g_hcp);
    cudaGetSymbolAddress((void**)&p_h1p, g_h1p);
    cudaGetSymbolAddress((void**)&p_h2,  g_h2);
    cudaGetSymbolAddress((void**)&p_ba,  g_ba);
    cudaGetSymbolAddress((void**)&p_bb,  g_bb);
    cudaGetSymbolAddress((void**)&p_bo,  g_bo);
    cudaGetSymbolAddress((void**)&p_bf0, g_bf0);
    cudaGetSymbolAddress((void**)&p_bfa, g_bfa);
    cudaGetSymbolAddress((void**)&p_bfb, g_bfb);
    cudaGetSymbolAddress((void**)&p_bfo, g_bfo);

    const size_t sm0  = (size_t)2 * 128 * (FIN + 8) * sizeof(__half);   // BM=128,K=64, split A
    const size_t sm16 = (size_t)     64 * (HH  + 8) * sizeof(__half);   // BM=64, K=128, fp16 A
    const size_t sm32 = (size_t)2 * 128 * (HH  + 8) * sizeof(__half);   // BM=128,K=128, split A
    const size_t smf  = ((size_t)HH*HH + 2*16*HH + 32) * sizeof(float); // fold0_bfrag
    cudaFuncSetAttribute(gemm_tc<128,FIN,HH,true,0,true,false>,     cudaFuncAttributeMaxDynamicSharedMemorySize, (int)sm0);
    cudaFuncSetAttribute(gemm_tc<64,HH,HH,false,-1,true,true>,      cudaFuncAttributeMaxDynamicSharedMemorySize, (int)sm16);
    cudaFuncSetAttribute(gemm_tc<64,HH,HH,true,2,false,true>,       cudaFuncAttributeMaxDynamicSharedMemorySize, (int)sm16);
    cudaFuncSetAttribute(gemm_tc<128,HH,FOUT,false,-1,false,false>, cudaFuncAttributeMaxDynamicSharedMemorySize, (int)sm32);
    cudaFuncSetAttribute(fold0_bfrag_kernel, cudaFuncAttributeMaxDynamicSharedMemorySize, (int)smf);

    const int EG = (BB*EE/4 + 255) / 256;   // grid for 4-edge-per-thread kernels
    bool fork = g_side.ok;

    if (fork) {
        // fork immediately: bucket zero + edge build on side stream
        cudaEventRecord(g_side.eFork, 0);
        cudaStreamWaitEvent(g_side.s, g_side.eFork, 0);
        zero_cnt_kernel<<<TOT/256, 256, 0, g_side.s>>>();
        scatter_kernel<<<EG, 256, 0, g_side.s>>>(erow, ecol, evl);
        cudaEventRecord(g_side.eJoin, g_side.s);
    } else {
        zero_cnt_kernel<<<TOT/256, 256>>>();
        scatter_kernel<<<EG, 256>>>(erow, ecol, evl);
    }

    // main chain
    prep0_kernel<<<HH/8 + 1, 128>>>(W0, p_bf0, b1, b2);

    // h0 = relu(x@W0 + b0) with bn0 stats  (fp16 out)
    gemm_tc<128,FIN,HH,true,0,true,false><<<TOT/128, 256, sm0>>>(x, p_bf0, b0, p_h0p);

    // fused fold: frag(diag(s0)*(W02@Wc)) + ba
    fold0_bfrag_kernel<<<HH/16, 256, smf>>>(bn0w, bn0b, W02, Wc, b02, bc, p_bfa);

    // hc = h0 @ Wa + ba   (fp16 in, fp16 out, 2-term)
    gemm_tc<64,HH,HH,false,-1,true,true><<<TOT/64, 256, sm16>>>(p_h0p, p_bfa, p_ba, p_hcp);

    if (fork) cudaStreamWaitEvent(0, g_side.eJoin, 0);   // join edge-build branch

    // SGC aggregate (+mask, relu, bnc stats) -> h1 fp16
    agg_kernel<<<TOT/8, 128>>>(nn);

    // fused fold bnc into W1 -> fragment table + bias (bb pre-seeded with b1)
    fold_bfrag_kernel<HH,HH><<<dim3(HH/8, 2), 128>>>(bncw, bncb, 1, W1, p_bfb, p_bb);

    // h2 = relu(h1 @ Wb + bb), bn1 stats fused  (fp16 in, fp32 out, 2-term)
    gemm_tc<64,HH,HH,true,2,false,true><<<TOT/64, 256, sm16>>>(p_h1p, p_bfb, p_bb, p_h2);

    // fused fold bn1 into W2 -> fragment table + bias (bo pre-seeded with b2)
    fold_bfrag_kernel<HH,FOUT><<<dim3(FOUT/8, 2), 128>>>(bn1w, bn1b, 2, W2, p_bfo, p_bo);

    // out = h2 @ Wo + bo   (fp32 in 3-term, fp32 out)
    gemm_tc<128,HH,FOUT,false,-1,false,false><<<TOT/128, 256, sm32>>>(p_h2, p_bfo, p_bo, out);
}